// round 14
// baseline (speedup 1.0000x reference)
#include <cuda_runtime.h>
#include <cstdint>

#define NNODES 100000
#define NEDGES 640000
#define FIN 128
#define FOUT 64
#define BN_EPS 1e-5f

// ---------------- scratch (static device globals; no runtime allocation) ----
__device__ float g_h[(size_t)NNODES * FIN];     // x @ W_gcn
__device__ float g_agg[(size_t)NNODES * FIN];   // aggregated messages
__device__ float g_t[(size_t)NNODES * FOUT];    // hidden after GEMM2
__device__ int   g_degi[NNODES];
__device__ float g_dinv[NNODES];
__device__ int   g_off[NNODES + 1];
__device__ int   g_cursor[NNODES];
__device__ int   g_alloc;
__device__ int   g_elist[NEDGES];
__device__ float g_sum1[FIN], g_sq1[FIN];
__device__ float g_sum2[FOUT], g_sq2[FOUT];

// ---------------- zero ------------------------------------------------------
__global__ void zero_kernel(int M) {
    int i = blockIdx.x * blockDim.x + threadIdx.x;
    for (int j = i; j < M; j += gridDim.x * blockDim.x) g_degi[j] = 0;
    if (i < FIN)  { g_sum1[i] = 0.f; g_sq1[i] = 0.f; }
    if (i < FOUT) { g_sum2[i] = 0.f; g_sq2[i] = 0.f; }
    if (i == 0) g_alloc = 0;
}

// ---------------- in-degree count -------------------------------------------
__global__ void deg_kernel(const int* __restrict__ dst, int E, int M) {
    int e = blockIdx.x * blockDim.x + threadIdx.x;
    if (e < E) {
        int d = dst[e];
        if ((unsigned)d < (unsigned)M) atomicAdd(&g_degi[d], 1);
    }
}

// ---------------- CSR segment allocation (warp-aggregated) ------------------
__global__ void alloc_kernel(int M) {
    int i = blockIdx.x * blockDim.x + threadIdx.x;
    int lane = threadIdx.x & 31;
    int deg = 0;
    if (i < M) deg = g_degi[i];
    int incl = deg;
    #pragma unroll
    for (int o = 1; o < 32; o <<= 1) {
        int v = __shfl_up_sync(0xffffffffu, incl, o);
        if (lane >= o) incl += v;
    }
    int total = __shfl_sync(0xffffffffu, incl, 31);
    int base = 0;
    if (lane == 0) base = atomicAdd(&g_alloc, total);
    base = __shfl_sync(0xffffffffu, base, 0);
    if (i < M) {
        int o = base + incl - deg;
        g_off[i] = o;
        g_cursor[i] = o;
        g_dinv[i] = rsqrtf((float)deg + 1.0f);  // +1 = self loop
    }
}

// ---------------- edge-list fill --------------------------------------------
__global__ void fill_kernel(const int* __restrict__ src, const int* __restrict__ dst,
                            int E, int M) {
    int e = blockIdx.x * blockDim.x + threadIdx.x;
    if (e < E) {
        int s = src[e];
        int d = dst[e];
        if ((unsigned)s < (unsigned)M && (unsigned)d < (unsigned)M) {
            int p = atomicAdd(&g_cursor[d], 1);
            g_elist[p] = s;
        }
    }
}

// ---------------- gather (edge ILP=2) ---------------------------------------
__global__ void gather_kernel(int M) {
    int warp = (blockIdx.x * blockDim.x + threadIdx.x) >> 5;
    int lane = threadIdx.x & 31;
    if (warp >= M) return;
    int d = warp;
    int e0 = g_off[d];
    int e1 = g_cursor[d];
    float4 acc0 = make_float4(0.f, 0.f, 0.f, 0.f);
    float4 acc1 = make_float4(0.f, 0.f, 0.f, 0.f);
    int e = e0;
    for (; e + 1 < e1; e += 2) {
        int s0 = g_elist[e];
        int s1 = g_elist[e + 1];
        float w0 = g_dinv[s0];
        float w1 = g_dinv[s1];
        float4 v0 = *(const float4*)&g_h[(size_t)s0 * FIN + lane * 4];
        float4 v1 = *(const float4*)&g_h[(size_t)s1 * FIN + lane * 4];
        acc0.x = fmaf(v0.x, w0, acc0.x); acc1.x = fmaf(v1.x, w1, acc1.x);
        acc0.y = fmaf(v0.y, w0, acc0.y); acc1.y = fmaf(v1.y, w1, acc1.y);
        acc0.z = fmaf(v0.z, w0, acc0.z); acc1.z = fmaf(v1.z, w1, acc1.z);
        acc0.w = fmaf(v0.w, w0, acc0.w); acc1.w = fmaf(v1.w, w1, acc1.w);
    }
    if (e < e1) {
        int s0 = g_elist[e];
        float w0 = g_dinv[s0];
        float4 v0 = *(const float4*)&g_h[(size_t)s0 * FIN + lane * 4];
        acc0.x = fmaf(v0.x, w0, acc0.x);
        acc0.y = fmaf(v0.y, w0, acc0.y);
        acc0.z = fmaf(v0.z, w0, acc0.z);
        acc0.w = fmaf(v0.w, w0, acc0.w);
    }
    float wd = g_dinv[d];
    float4 vs = *(const float4*)&g_h[(size_t)d * FIN + lane * 4];
    float4 o;
    o.x = wd * (acc0.x + acc1.x) + wd * wd * vs.x;
    o.y = wd * (acc0.y + acc1.y) + wd * wd * vs.y;
    o.z = wd * (acc0.z + acc1.z) + wd * wd * vs.z;
    o.w = wd * (acc0.w + acc1.w) + wd * wd * vs.w;
    *(float4*)&g_agg[(size_t)d * FIN + lane * 4] = o;
}

// ---------------- per-column sum / sumsq ------------------------------------
template <int F>
__global__ void stats_kernel(const float* __restrict__ X, int M,
                             float* __restrict__ sum, float* __restrict__ sq) {
    constexpr int RP = 256 / F;
    int col  = threadIdx.x % F;
    int rsub = threadIdx.x / F;
    float s = 0.f, q = 0.f;
    for (int r = blockIdx.x * RP + rsub; r < M; r += gridDim.x * RP) {
        float v = X[(size_t)r * F + col];
        s += v; q += v * v;
    }
    __shared__ float sh[256];
    sh[threadIdx.x] = s; __syncthreads();
    if (rsub == 0) {
        #pragma unroll
        for (int k = 1; k < RP; k++) s += sh[k * F + col];
    }
    __syncthreads();
    sh[threadIdx.x] = q; __syncthreads();
    if (rsub == 0) {
        #pragma unroll
        for (int k = 1; k < RP; k++) q += sh[k * F + col];
        atomicAdd(&sum[col], s);
        atomicAdd(&sq[col],  q);
    }
}

// ---------------- tf32 helpers ----------------------------------------------
__device__ __forceinline__ uint32_t f_tf32(float x) {
    uint32_t y;
    asm("cvt.rna.tf32.f32 %0, %1;" : "=r"(y) : "f"(x));
    return y;
}

#define MMA_TF32(acc, a0, a1, a2, a3, b0, b1)                                  \
    asm volatile(                                                              \
        "mma.sync.aligned.m16n8k8.row.col.f32.tf32.tf32.f32 "                  \
        "{%0,%1,%2,%3}, {%4,%5,%6,%7}, {%8,%9}, {%0,%1,%2,%3};"                \
        : "+f"((acc)[0]), "+f"((acc)[1]), "+f"((acc)[2]), "+f"((acc)[3])       \
        : "r"(a0), "r"(a1), "r"(a2), "r"(a3), "r"(b0), "r"(b1))

// ---------------- tf32 tensor GEMM1: h = x @ W  (M x 128 x 128) -------------
__global__ __launch_bounds__(256) void tgemm1_kernel(
    const float* __restrict__ A, const float* __restrict__ B, float* __restrict__ C, int M) {
    constexpr int BM = 128, BN = 128, BK = 32;
    __shared__ uint32_t As[BM][BK + 4];
    __shared__ uint32_t Bs[BK][BN + 8];

    int tid = threadIdx.x;
    int lane = tid & 31, wid = tid >> 5;
    int wr = wid & 3, wc = wid >> 2;
    int m0 = wr * 32, n0 = wc * 64;
    int row0 = blockIdx.x * BM;
    int grp = lane >> 2, tig = lane & 3;

    float acc[2][8][4];
    #pragma unroll
    for (int i = 0; i < 2; i++)
        #pragma unroll
        for (int j = 0; j < 8; j++)
            #pragma unroll
            for (int r = 0; r < 4; r++) acc[i][j][r] = 0.f;

    for (int k0 = 0; k0 < 128; k0 += BK) {
        #pragma unroll
        for (int p = 0; p < 4; p++) {
            int f = tid + p * 256;
            int r = f >> 3;
            int c4 = (f & 7) * 4;
            float4 v = make_float4(0.f, 0.f, 0.f, 0.f);
            if (row0 + r < M) v = *(const float4*)&A[(size_t)(row0 + r) * 128 + k0 + c4];
            As[r][c4 + 0] = f_tf32(v.x); As[r][c4 + 1] = f_tf32(v.y);
            As[r][c4 + 2] = f_tf32(v.z); As[r][c4 + 3] = f_tf32(v.w);
        }
        #pragma unroll
        for (int p = 0; p < 4; p++) {
            int f = tid + p * 256;
            int kr = f >> 5;
            int c4 = (f & 31) * 4;
            float4 v = *(const float4*)&B[(size_t)(k0 + kr) * 128 + c4];
            Bs[kr][c4 + 0] = f_tf32(v.x); Bs[kr][c4 + 1] = f_tf32(v.y);
            Bs[kr][c4 + 2] = f_tf32(v.z); Bs[kr][c4 + 3] = f_tf32(v.w);
        }
        __syncthreads();

        #pragma unroll
        for (int ks = 0; ks < BK / 8; ks++) {
            int kb = ks * 8;
            uint32_t a[2][4];
            #pragma unroll
            for (int mi = 0; mi < 2; mi++) {
                int r = m0 + mi * 16 + grp;
                a[mi][0] = As[r    ][kb + tig    ];
                a[mi][1] = As[r + 8][kb + tig    ];
                a[mi][2] = As[r    ][kb + tig + 4];
                a[mi][3] = As[r + 8][kb + tig + 4];
            }
            uint32_t b[8][2];
            #pragma unroll
            for (int ni = 0; ni < 8; ni++) {
                int n = n0 + ni * 8 + grp;
                b[ni][0] = Bs[kb + tig    ][n];
                b[ni][1] = Bs[kb + tig + 4][n];
            }
            #pragma unroll
            for (int mi = 0; mi < 2; mi++)
                #pragma unroll
                for (int ni = 0; ni < 8; ni++)
                    MMA_TF32(acc[mi][ni], a[mi][0], a[mi][1], a[mi][2], a[mi][3],
                             b[ni][0], b[ni][1]);
        }
        __syncthreads();
    }

    #pragma unroll
    for (int mi = 0; mi < 2; mi++) {
        int rbase = row0 + m0 + mi * 16 + grp;
        #pragma unroll
        for (int ni = 0; ni < 8; ni++) {
            int col = n0 + ni * 8 + 2 * tig;
            if (rbase < M) {
                float2 v0 = make_float2(acc[mi][ni][0], acc[mi][ni][1]);
                *(float2*)&C[(size_t)rbase * 128 + col] = v0;
            }
            if (rbase + 8 < M) {
                float2 v1 = make_float2(acc[mi][ni][2], acc[mi][ni][3]);
                *(float2*)&C[(size_t)(rbase + 8) * 128 + col] = v1;
            }
        }
    }
}

// ---------------- tf32 tensor GEMM2: t = relu(a1*agg+c1) @ W1 (Mx128x64) ----
// BN1 coefficients computed inline from sum/sq (finalize folded in).
__global__ __launch_bounds__(256) void tgemm2_kernel(
    const float* __restrict__ A, const float* __restrict__ B, float* __restrict__ C,
    int M, const float* __restrict__ sum, const float* __restrict__ sq,
    const float* __restrict__ gamma, const float* __restrict__ beta) {
    constexpr int BM = 128, BN = 64, BK = 32, K = 128;
    __shared__ uint32_t As[BM][BK + 4];
    __shared__ uint32_t Bs[BK][BN + 8];
    __shared__ float s_sc[K], s_sh[K];

    int tid = threadIdx.x;
    if (tid < K) {
        float mean = sum[tid] / (float)M;
        float var  = sq[tid] / (float)M - mean * mean;
        float s = gamma[tid] * rsqrtf(var + BN_EPS);
        s_sc[tid] = s;
        s_sh[tid] = beta[tid] - mean * s;
    }

    int lane = tid & 31, wid = tid >> 5;
    int wr = wid & 3, wc = wid >> 2;
    int m0 = wr * 32, n0 = wc * 32;
    int row0 = blockIdx.x * BM;
    int grp = lane >> 2, tig = lane & 3;
    __syncthreads();

    float acc[2][4][4];
    #pragma unroll
    for (int i = 0; i < 2; i++)
        #pragma unroll
        for (int j = 0; j < 4; j++)
            #pragma unroll
            for (int r = 0; r < 4; r++) acc[i][j][r] = 0.f;

    for (int k0 = 0; k0 < K; k0 += BK) {
        #pragma unroll
        for (int p = 0; p < 4; p++) {
            int f = tid + p * 256;
            int r = f >> 3;
            int c4 = (f & 7) * 4;
            float4 v = make_float4(0.f, 0.f, 0.f, 0.f);
            if (row0 + r < M) v = *(const float4*)&A[(size_t)(row0 + r) * K + k0 + c4];
            int kb = k0 + c4;
            v.x = fmaxf(fmaf(v.x, s_sc[kb + 0], s_sh[kb + 0]), 0.f);
            v.y = fmaxf(fmaf(v.y, s_sc[kb + 1], s_sh[kb + 1]), 0.f);
            v.z = fmaxf(fmaf(v.z, s_sc[kb + 2], s_sh[kb + 2]), 0.f);
            v.w = fmaxf(fmaf(v.w, s_sc[kb + 3], s_sh[kb + 3]), 0.f);
            As[r][c4 + 0] = f_tf32(v.x); As[r][c4 + 1] = f_tf32(v.y);
            As[r][c4 + 2] = f_tf32(v.z); As[r][c4 + 3] = f_tf32(v.w);
        }
        #pragma unroll
        for (int p = 0; p < 2; p++) {
            int f = tid + p * 256;
            int kr = f >> 4;
            int c4 = (f & 15) * 4;
            float4 v = *(const float4*)&B[(size_t)(k0 + kr) * BN + c4];
            Bs[kr][c4 + 0] = f_tf32(v.x); Bs[kr][c4 + 1] = f_tf32(v.y);
            Bs[kr][c4 + 2] = f_tf32(v.z); Bs[kr][c4 + 3] = f_tf32(v.w);
        }
        __syncthreads();

        #pragma unroll
        for (int ks = 0; ks < BK / 8; ks++) {
            int kb = ks * 8;
            uint32_t a[2][4];
            #pragma unroll
            for (int mi = 0; mi < 2; mi++) {
                int r = m0 + mi * 16 + grp;
                a[mi][0] = As[r    ][kb + tig    ];
                a[mi][1] = As[r + 8][kb + tig    ];
                a[mi][2] = As[r    ][kb + tig + 4];
                a[mi][3] = As[r + 8][kb + tig + 4];
            }
            uint32_t b[4][2];
            #pragma unroll
            for (int ni = 0; ni < 4; ni++) {
                int n = n0 + ni * 8 + grp;
                b[ni][0] = Bs[kb + tig    ][n];
                b[ni][1] = Bs[kb + tig + 4][n];
            }
            #pragma unroll
            for (int mi = 0; mi < 2; mi++)
                #pragma unroll
                for (int ni = 0; ni < 4; ni++)
                    MMA_TF32(acc[mi][ni], a[mi][0], a[mi][1], a[mi][2], a[mi][3],
                             b[ni][0], b[ni][1]);
        }
        __syncthreads();
    }

    #pragma unroll
    for (int mi = 0; mi < 2; mi++) {
        int rbase = row0 + m0 + mi * 16 + grp;
        #pragma unroll
        for (int ni = 0; ni < 4; ni++) {
            int col = n0 + ni * 8 + 2 * tig;
            if (rbase < M) {
                float2 v0 = make_float2(acc[mi][ni][0], acc[mi][ni][1]);
                *(float2*)&C[(size_t)rbase * BN + col] = v0;
            }
            if (rbase + 8 < M) {
                float2 v1 = make_float2(acc[mi][ni][2], acc[mi][ni][3]);
                *(float2*)&C[(size_t)(rbase + 8) * BN + col] = v1;
            }
        }
    }
}

// ---------------- 3xtf32 tensor GEMM3 (error-compensated, fp32-class) -------
// out = relu(a2*t+c2) @ W2 + b2; BN2 coefficients computed inline.
__global__ __launch_bounds__(256) void tgemm3_kernel(
    const float* __restrict__ A, const float* __restrict__ B, float* __restrict__ C,
    int M, const float* __restrict__ sum, const float* __restrict__ sq,
    const float* __restrict__ gamma, const float* __restrict__ beta,
    const float* __restrict__ bias) {
    constexpr int BM = 128, BN = 64, BK = 16, K = 64;
    __shared__ uint32_t Ah[BM][BK + 4], Al[BM][BK + 4];
    __shared__ uint32_t Bh[BK][BN + 8], Bl[BK][BN + 8];
    __shared__ float s_sc[K], s_sh[K], s_b[BN];

    int tid = threadIdx.x;
    if (tid < K) {
        float mean = sum[tid] / (float)M;
        float var  = sq[tid] / (float)M - mean * mean;
        float s = gamma[tid] * rsqrtf(var + BN_EPS);
        s_sc[tid] = s;
        s_sh[tid] = beta[tid] - mean * s;
    }
    if (tid < BN) s_b[tid] = bias[tid];

    int lane = tid & 31, wid = tid >> 5;
    int wr = wid & 3, wc = wid >> 2;
    int m0 = wr * 32, n0 = wc * 32;
    int row0 = blockIdx.x * BM;
    int grp = lane >> 2, tig = lane & 3;
    __syncthreads();

    float acc[2][4][4];
    #pragma unroll
    for (int i = 0; i < 2; i++)
        #pragma unroll
        for (int j = 0; j < 4; j++)
            #pragma unroll
            for (int r = 0; r < 4; r++) acc[i][j][r] = 0.f;

    for (int k0 = 0; k0 < K; k0 += BK) {
        #pragma unroll
        for (int p = 0; p < 2; p++) {
            int f = tid + p * 256;
            int r = f >> 2;
            int c4 = (f & 3) * 4;
            float4 v = make_float4(0.f, 0.f, 0.f, 0.f);
            if (row0 + r < M) v = *(const float4*)&A[(size_t)(row0 + r) * K + k0 + c4];
            int kb = k0 + c4;
            v.x = fmaxf(fmaf(v.x, s_sc[kb + 0], s_sh[kb + 0]), 0.f);
            v.y = fmaxf(fmaf(v.y, s_sc[kb + 1], s_sh[kb + 1]), 0.f);
            v.z = fmaxf(fmaf(v.z, s_sc[kb + 2], s_sh[kb + 2]), 0.f);
            v.w = fmaxf(fmaf(v.w, s_sc[kb + 3], s_sh[kb + 3]), 0.f);
            uint32_t hx = f_tf32(v.x), hy = f_tf32(v.y), hz = f_tf32(v.z), hw = f_tf32(v.w);
            Ah[r][c4 + 0] = hx; Ah[r][c4 + 1] = hy; Ah[r][c4 + 2] = hz; Ah[r][c4 + 3] = hw;
            Al[r][c4 + 0] = f_tf32(v.x - __uint_as_float(hx));
            Al[r][c4 + 1] = f_tf32(v.y - __uint_as_float(hy));
            Al[r][c4 + 2] = f_tf32(v.z - __uint_as_float(hz));
            Al[r][c4 + 3] = f_tf32(v.w - __uint_as_float(hw));
        }
        {
            int kr = tid >> 4;
            int c4 = (tid & 15) * 4;
            float4 v = *(const float4*)&B[(size_t)(k0 + kr) * BN + c4];
            uint32_t hx = f_tf32(v.x), hy = f_tf32(v.y), hz = f_tf32(v.z), hw = f_tf32(v.w);
            Bh[kr][c4 + 0] = hx; Bh[kr][c4 + 1] = hy; Bh[kr][c4 + 2] = hz; Bh[kr][c4 + 3] = hw;
            Bl[kr][c4 + 0] = f_tf32(v.x - __uint_as_float(hx));
            Bl[kr][c4 + 1] = f_tf32(v.y - __uint_as_float(hy));
            Bl[kr][c4 + 2] = f_tf32(v.z - __uint_as_float(hz));
            Bl[kr][c4 + 3] = f_tf32(v.w - __uint_as_float(hw));
        }
        __syncthreads();

        #pragma unroll
        for (int ks = 0; ks < BK / 8; ks++) {
            int kb = ks * 8;
            uint32_t ah[2][4], al[2][4];
            #pragma unroll
            for (int mi = 0; mi < 2; mi++) {
                int r = m0 + mi * 16 + grp;
                ah[mi][0] = Ah[r    ][kb + tig    ];
                ah[mi][1] = Ah[r + 8][kb + tig    ];
                ah[mi][2] = Ah[r    ][kb + tig + 4];
                ah[mi][3] = Ah[r + 8][kb + tig + 4];
                al[mi][0] = Al[r    ][kb + tig    ];
                al[mi][1] = Al[r + 8][kb + tig    ];
                al[mi][2] = Al[r    ][kb + tig + 4];
                al[mi][3] = Al[r + 8][kb + tig + 4];
            }
            uint32_t bh[4][2], bl[4][2];
            #pragma unroll
            for (int ni = 0; ni < 4; ni++) {
                int n = n0 + ni * 8 + grp;
                bh[ni][0] = Bh[kb + tig    ][n];
                bh[ni][1] = Bh[kb + tig + 4][n];
                bl[ni][0] = Bl[kb + tig    ][n];
                bl[ni][1] = Bl[kb + tig + 4][n];
            }
            #pragma unroll
            for (int mi = 0; mi < 2; mi++)
                #pragma unroll
                for (int ni = 0; ni < 4; ni++) {
                    MMA_TF32(acc[mi][ni], al[mi][0], al[mi][1], al[mi][2], al[mi][3],
                             bh[ni][0], bh[ni][1]);
                    MMA_TF32(acc[mi][ni], ah[mi][0], ah[mi][1], ah[mi][2], ah[mi][3],
                             bl[ni][0], bl[ni][1]);
                    MMA_TF32(acc[mi][ni], ah[mi][0], ah[mi][1], ah[mi][2], ah[mi][3],
                             bh[ni][0], bh[ni][1]);
                }
        }
        __syncthreads();
    }

    #pragma unroll
    for (int mi = 0; mi < 2; mi++) {
        int rbase = row0 + m0 + mi * 16 + grp;
        #pragma unroll
        for (int ni = 0; ni < 4; ni++) {
            int col = n0 + ni * 8 + 2 * tig;
            float b0 = s_b[col], b1 = s_b[col + 1];
            if (rbase < M) {
                float2 v0 = make_float2(acc[mi][ni][0] + b0, acc[mi][ni][1] + b1);
                *(float2*)&C[(size_t)rbase * BN + col] = v0;
            }
            if (rbase + 8 < M) {
                float2 v1 = make_float2(acc[mi][ni][2] + b0, acc[mi][ni][3] + b1);
                *(float2*)&C[(size_t)(rbase + 8) * BN + col] = v1;
            }
        }
    }
}

// ---------------- launch ----------------------------------------------------
extern "C" void kernel_launch(void* const* d_in, const int* in_sizes, int n_in,
                              void* d_out, int out_size) {
    const float* x     = (const float*)d_in[0];
    const int*   ei    = (const int*)d_in[1];
    const float* W_gcn = (const float*)d_in[2];
    // d_in[3] = b_gcn : exactly absorbed by BN1 (mean-subtraction) -> unused
    const float* bn_g  = (const float*)d_in[4];
    const float* bn_b  = (const float*)d_in[5];
    const float* W1    = (const float*)d_in[6];
    // d_in[7] = b1    : exactly absorbed by BN2 -> unused
    const float* mg    = (const float*)d_in[8];
    const float* mb    = (const float*)d_in[9];
    const float* W2    = (const float*)d_in[10];
    const float* b2    = (const float*)d_in[11];
    float* out = (float*)d_out;

    int M = in_sizes[0] / FIN;
    int E = in_sizes[1] / 2;
    const int* src = ei;
    const int* dst = ei + E;

    void *p_h, *p_agg, *p_t, *p_sum1, *p_sq1, *p_sum2, *p_sq2;
    cudaGetSymbolAddress(&p_h, g_h);
    cudaGetSymbolAddress(&p_agg, g_agg);
    cudaGetSymbolAddress(&p_t, g_t);
    cudaGetSymbolAddress(&p_sum1, g_sum1);
    cudaGetSymbolAddress(&p_sq1, g_sq1);
    cudaGetSymbolAddress(&p_sum2, g_sum2);
    cudaGetSymbolAddress(&p_sq2, g_sq2);

    // side stream + fork/join events; created once, reused every call.
    static cudaStream_t s_side = nullptr;
    static cudaEvent_t s_evFork = nullptr, s_evJoin = nullptr;
    if (s_side == nullptr) {
        cudaStreamCreateWithFlags(&s_side, cudaStreamNonBlocking);
        cudaEventCreateWithFlags(&s_evFork, cudaEventDisableTiming);
        cudaEventCreateWithFlags(&s_evJoin, cudaEventDisableTiming);
    }

    // main: zero (needed by both branches)
    zero_kernel<<<256, 256>>>(M);

    // fork: index machinery on side stream, overlapped with tgemm1 on main
    cudaEventRecord(s_evFork, 0);
    cudaStreamWaitEvent(s_side, s_evFork, 0);
    deg_kernel<<<(E + 255) / 256, 256, 0, s_side>>>(dst, E, M);
    alloc_kernel<<<(M + 255) / 256, 256, 0, s_side>>>(M);
    fill_kernel<<<(E + 255) / 256, 256, 0, s_side>>>(src, dst, E, M);
    cudaEventRecord(s_evJoin, s_side);

    // main: GEMM1 (tf32): h = x @ W_gcn
    tgemm1_kernel<<<(M + 127) / 128, 256>>>(x, W_gcn, (float*)p_h, M);

    // join: gather needs h + CSR + dinv
    cudaStreamWaitEvent(0, s_evJoin, 0);
    gather_kernel<<<(M * 32 + 255) / 256, 256>>>(M);

    // BN1 stats (finalize folded into tgemm2)
    stats_kernel<FIN><<<1024, 256>>>((const float*)p_agg, M, (float*)p_sum1, (float*)p_sq1);

    // GEMM2 (tf32, inline BN1): t = relu(BN1(agg)) @ W1
    tgemm2_kernel<<<(M + 127) / 128, 256>>>(
        (const float*)p_agg, W1, (float*)p_t, M,
        (const float*)p_sum1, (const float*)p_sq1, bn_g, bn_b);

    // BN2 stats (finalize folded into tgemm3)
    stats_kernel<FOUT><<<1024, 256>>>((const float*)p_t, M, (float*)p_sum2, (float*)p_sq2);

    // GEMM3 (3xtf32, inline BN2): out = relu(BN2(t)) @ W2 + b2
    tgemm3_kernel<<<(M + 127) / 128, 256>>>(
        (const float*)p_t, W2, out, M,
        (const float*)p_sum2, (const float*)p_sq2, mg, mb, b2);
}

// round 15
// speedup vs baseline: 1.0713x; 1.0713x over previous
#include <cuda_runtime.h>
#include <cstdint>

#define NNODES 100000
#define NEDGES 640000
#define FIN 128
#define FOUT 64
#define BN_EPS 1e-5f

// ---------------- scratch (static device globals; no runtime allocation) ----
__device__ float g_h[(size_t)NNODES * FIN];     // x @ W_gcn
__device__ float g_agg[(size_t)NNODES * FIN];   // aggregated messages
__device__ float g_t[(size_t)NNODES * FOUT];    // hidden after GEMM2
__device__ int   g_degi[NNODES];
__device__ float g_dinv[NNODES];
__device__ int   g_off[NNODES + 1];
__device__ int   g_cursor[NNODES];
__device__ int   g_alloc;
__device__ int   g_elist[NEDGES];
__device__ float g_sum1[FIN], g_sq1[FIN];
__device__ float g_sum2[FOUT], g_sq2[FOUT];

// ---------------- zero ------------------------------------------------------
__global__ void zero_kernel(int M) {
    int i = blockIdx.x * blockDim.x + threadIdx.x;
    for (int j = i; j < M; j += gridDim.x * blockDim.x) g_degi[j] = 0;
    if (i < FIN)  { g_sum1[i] = 0.f; g_sq1[i] = 0.f; }
    if (i < FOUT) { g_sum2[i] = 0.f; g_sq2[i] = 0.f; }
    if (i == 0) g_alloc = 0;
}

// ---------------- in-degree count -------------------------------------------
__global__ void deg_kernel(const int* __restrict__ dst, int E, int M) {
    int e = blockIdx.x * blockDim.x + threadIdx.x;
    if (e < E) {
        int d = dst[e];
        if ((unsigned)d < (unsigned)M) atomicAdd(&g_degi[d], 1);
    }
}

// ---------------- CSR segment allocation (warp-aggregated) ------------------
__global__ void alloc_kernel(int M) {
    int i = blockIdx.x * blockDim.x + threadIdx.x;
    int lane = threadIdx.x & 31;
    int deg = 0;
    if (i < M) deg = g_degi[i];
    int incl = deg;
    #pragma unroll
    for (int o = 1; o < 32; o <<= 1) {
        int v = __shfl_up_sync(0xffffffffu, incl, o);
        if (lane >= o) incl += v;
    }
    int total = __shfl_sync(0xffffffffu, incl, 31);
    int base = 0;
    if (lane == 0) base = atomicAdd(&g_alloc, total);
    base = __shfl_sync(0xffffffffu, base, 0);
    if (i < M) {
        int o = base + incl - deg;
        g_off[i] = o;
        g_cursor[i] = o;
        g_dinv[i] = rsqrtf((float)deg + 1.0f);  // +1 = self loop
    }
}

// ---------------- edge-list fill --------------------------------------------
__global__ void fill_kernel(const int* __restrict__ src, const int* __restrict__ dst,
                            int E, int M) {
    int e = blockIdx.x * blockDim.x + threadIdx.x;
    if (e < E) {
        int s = src[e];
        int d = dst[e];
        if ((unsigned)s < (unsigned)M && (unsigned)d < (unsigned)M) {
            int p = atomicAdd(&g_cursor[d], 1);
            g_elist[p] = s;
        }
    }
}

// ---------------- gather (R4/R13 exact — plain loop) ------------------------
__global__ void gather_kernel(int M) {
    int warp = (blockIdx.x * blockDim.x + threadIdx.x) >> 5;
    int lane = threadIdx.x & 31;
    if (warp >= M) return;
    int d = warp;
    int e0 = g_off[d];
    int e1 = g_cursor[d];
    float4 acc = make_float4(0.f, 0.f, 0.f, 0.f);
    for (int e = e0; e < e1; e++) {
        int s = g_elist[e];
        float ws = g_dinv[s];
        float4 v = *(const float4*)&g_h[(size_t)s * FIN + lane * 4];
        acc.x = fmaf(v.x, ws, acc.x);
        acc.y = fmaf(v.y, ws, acc.y);
        acc.z = fmaf(v.z, ws, acc.z);
        acc.w = fmaf(v.w, ws, acc.w);
    }
    float wd = g_dinv[d];
    float4 vs = *(const float4*)&g_h[(size_t)d * FIN + lane * 4];
    float4 o;
    o.x = wd * acc.x + wd * wd * vs.x;
    o.y = wd * acc.y + wd * wd * vs.y;
    o.z = wd * acc.z + wd * wd * vs.z;
    o.w = wd * acc.w + wd * wd * vs.w;
    *(float4*)&g_agg[(size_t)d * FIN + lane * 4] = o;
}

// ---------------- per-column sum / sumsq ------------------------------------
template <int F>
__global__ void stats_kernel(const float* __restrict__ X, int M,
                             float* __restrict__ sum, float* __restrict__ sq) {
    constexpr int RP = 256 / F;
    int col  = threadIdx.x % F;
    int rsub = threadIdx.x / F;
    float s = 0.f, q = 0.f;
    for (int r = blockIdx.x * RP + rsub; r < M; r += gridDim.x * RP) {
        float v = X[(size_t)r * F + col];
        s += v; q += v * v;
    }
    __shared__ float sh[256];
    sh[threadIdx.x] = s; __syncthreads();
    if (rsub == 0) {
        #pragma unroll
        for (int k = 1; k < RP; k++) s += sh[k * F + col];
    }
    __syncthreads();
    sh[threadIdx.x] = q; __syncthreads();
    if (rsub == 0) {
        #pragma unroll
        for (int k = 1; k < RP; k++) q += sh[k * F + col];
        atomicAdd(&sum[col], s);
        atomicAdd(&sq[col],  q);
    }
}

// ---------------- tf32 helpers ----------------------------------------------
__device__ __forceinline__ uint32_t f_tf32(float x) {
    uint32_t y;
    asm("cvt.rna.tf32.f32 %0, %1;" : "=r"(y) : "f"(x));
    return y;
}

#define MMA_TF32(acc, a0, a1, a2, a3, b0, b1)                                  \
    asm volatile(                                                              \
        "mma.sync.aligned.m16n8k8.row.col.f32.tf32.tf32.f32 "                  \
        "{%0,%1,%2,%3}, {%4,%5,%6,%7}, {%8,%9}, {%0,%1,%2,%3};"                \
        : "+f"((acc)[0]), "+f"((acc)[1]), "+f"((acc)[2]), "+f"((acc)[3])       \
        : "r"(a0), "r"(a1), "r"(a2), "r"(a3), "r"(b0), "r"(b1))

// ---------------- tf32 tensor GEMM1: h = x @ W  (M x 128 x 128) -------------
__global__ __launch_bounds__(256) void tgemm1_kernel(
    const float* __restrict__ A, const float* __restrict__ B, float* __restrict__ C, int M) {
    constexpr int BM = 128, BN = 128, BK = 32;
    __shared__ uint32_t As[BM][BK + 4];
    __shared__ uint32_t Bs[BK][BN + 8];

    int tid = threadIdx.x;
    int lane = tid & 31, wid = tid >> 5;
    int wr = wid & 3, wc = wid >> 2;
    int m0 = wr * 32, n0 = wc * 64;
    int row0 = blockIdx.x * BM;
    int grp = lane >> 2, tig = lane & 3;

    float acc[2][8][4];
    #pragma unroll
    for (int i = 0; i < 2; i++)
        #pragma unroll
        for (int j = 0; j < 8; j++)
            #pragma unroll
            for (int r = 0; r < 4; r++) acc[i][j][r] = 0.f;

    for (int k0 = 0; k0 < 128; k0 += BK) {
        #pragma unroll
        for (int p = 0; p < 4; p++) {
            int f = tid + p * 256;
            int r = f >> 3;
            int c4 = (f & 7) * 4;
            float4 v = make_float4(0.f, 0.f, 0.f, 0.f);
            if (row0 + r < M) v = *(const float4*)&A[(size_t)(row0 + r) * 128 + k0 + c4];
            As[r][c4 + 0] = f_tf32(v.x); As[r][c4 + 1] = f_tf32(v.y);
            As[r][c4 + 2] = f_tf32(v.z); As[r][c4 + 3] = f_tf32(v.w);
        }
        #pragma unroll
        for (int p = 0; p < 4; p++) {
            int f = tid + p * 256;
            int kr = f >> 5;
            int c4 = (f & 31) * 4;
            float4 v = *(const float4*)&B[(size_t)(k0 + kr) * 128 + c4];
            Bs[kr][c4 + 0] = f_tf32(v.x); Bs[kr][c4 + 1] = f_tf32(v.y);
            Bs[kr][c4 + 2] = f_tf32(v.z); Bs[kr][c4 + 3] = f_tf32(v.w);
        }
        __syncthreads();

        #pragma unroll
        for (int ks = 0; ks < BK / 8; ks++) {
            int kb = ks * 8;
            uint32_t a[2][4];
            #pragma unroll
            for (int mi = 0; mi < 2; mi++) {
                int r = m0 + mi * 16 + grp;
                a[mi][0] = As[r    ][kb + tig    ];
                a[mi][1] = As[r + 8][kb + tig    ];
                a[mi][2] = As[r    ][kb + tig + 4];
                a[mi][3] = As[r + 8][kb + tig + 4];
            }
            uint32_t b[8][2];
            #pragma unroll
            for (int ni = 0; ni < 8; ni++) {
                int n = n0 + ni * 8 + grp;
                b[ni][0] = Bs[kb + tig    ][n];
                b[ni][1] = Bs[kb + tig + 4][n];
            }
            #pragma unroll
            for (int mi = 0; mi < 2; mi++)
                #pragma unroll
                for (int ni = 0; ni < 8; ni++)
                    MMA_TF32(acc[mi][ni], a[mi][0], a[mi][1], a[mi][2], a[mi][3],
                             b[ni][0], b[ni][1]);
        }
        __syncthreads();
    }

    #pragma unroll
    for (int mi = 0; mi < 2; mi++) {
        int rbase = row0 + m0 + mi * 16 + grp;
        #pragma unroll
        for (int ni = 0; ni < 8; ni++) {
            int col = n0 + ni * 8 + 2 * tig;
            if (rbase < M) {
                float2 v0 = make_float2(acc[mi][ni][0], acc[mi][ni][1]);
                *(float2*)&C[(size_t)rbase * 128 + col] = v0;
            }
            if (rbase + 8 < M) {
                float2 v1 = make_float2(acc[mi][ni][2], acc[mi][ni][3]);
                *(float2*)&C[(size_t)(rbase + 8) * 128 + col] = v1;
            }
        }
    }
}

// ---------------- tf32 tensor GEMM2: t = relu(a1*agg+c1) @ W1 (Mx128x64) ----
// BN1 coefficients computed inline from sum/sq (finalize folded in).
__global__ __launch_bounds__(256) void tgemm2_kernel(
    const float* __restrict__ A, const float* __restrict__ B, float* __restrict__ C,
    int M, const float* __restrict__ sum, const float* __restrict__ sq,
    const float* __restrict__ gamma, const float* __restrict__ beta) {
    constexpr int BM = 128, BN = 64, BK = 32, K = 128;
    __shared__ uint32_t As[BM][BK + 4];
    __shared__ uint32_t Bs[BK][BN + 8];
    __shared__ float s_sc[K], s_sh[K];

    int tid = threadIdx.x;
    if (tid < K) {
        float mean = sum[tid] / (float)M;
        float var  = sq[tid] / (float)M - mean * mean;
        float s = gamma[tid] * rsqrtf(var + BN_EPS);
        s_sc[tid] = s;
        s_sh[tid] = beta[tid] - mean * s;
    }

    int lane = tid & 31, wid = tid >> 5;
    int wr = wid & 3, wc = wid >> 2;
    int m0 = wr * 32, n0 = wc * 32;
    int row0 = blockIdx.x * BM;
    int grp = lane >> 2, tig = lane & 3;
    __syncthreads();

    float acc[2][4][4];
    #pragma unroll
    for (int i = 0; i < 2; i++)
        #pragma unroll
        for (int j = 0; j < 4; j++)
            #pragma unroll
            for (int r = 0; r < 4; r++) acc[i][j][r] = 0.f;

    for (int k0 = 0; k0 < K; k0 += BK) {
        #pragma unroll
        for (int p = 0; p < 4; p++) {
            int f = tid + p * 256;
            int r = f >> 3;
            int c4 = (f & 7) * 4;
            float4 v = make_float4(0.f, 0.f, 0.f, 0.f);
            if (row0 + r < M) v = *(const float4*)&A[(size_t)(row0 + r) * K + k0 + c4];
            int kb = k0 + c4;
            v.x = fmaxf(fmaf(v.x, s_sc[kb + 0], s_sh[kb + 0]), 0.f);
            v.y = fmaxf(fmaf(v.y, s_sc[kb + 1], s_sh[kb + 1]), 0.f);
            v.z = fmaxf(fmaf(v.z, s_sc[kb + 2], s_sh[kb + 2]), 0.f);
            v.w = fmaxf(fmaf(v.w, s_sc[kb + 3], s_sh[kb + 3]), 0.f);
            As[r][c4 + 0] = f_tf32(v.x); As[r][c4 + 1] = f_tf32(v.y);
            As[r][c4 + 2] = f_tf32(v.z); As[r][c4 + 3] = f_tf32(v.w);
        }
        #pragma unroll
        for (int p = 0; p < 2; p++) {
            int f = tid + p * 256;
            int kr = f >> 4;
            int c4 = (f & 15) * 4;
            float4 v = *(const float4*)&B[(size_t)(k0 + kr) * BN + c4];
            Bs[kr][c4 + 0] = f_tf32(v.x); Bs[kr][c4 + 1] = f_tf32(v.y);
            Bs[kr][c4 + 2] = f_tf32(v.z); Bs[kr][c4 + 3] = f_tf32(v.w);
        }
        __syncthreads();

        #pragma unroll
        for (int ks = 0; ks < BK / 8; ks++) {
            int kb = ks * 8;
            uint32_t a[2][4];
            #pragma unroll
            for (int mi = 0; mi < 2; mi++) {
                int r = m0 + mi * 16 + grp;
                a[mi][0] = As[r    ][kb + tig    ];
                a[mi][1] = As[r + 8][kb + tig    ];
                a[mi][2] = As[r    ][kb + tig + 4];
                a[mi][3] = As[r + 8][kb + tig + 4];
            }
            uint32_t b[4][2];
            #pragma unroll
            for (int ni = 0; ni < 4; ni++) {
                int n = n0 + ni * 8 + grp;
                b[ni][0] = Bs[kb + tig    ][n];
                b[ni][1] = Bs[kb + tig + 4][n];
            }
            #pragma unroll
            for (int mi = 0; mi < 2; mi++)
                #pragma unroll
                for (int ni = 0; ni < 4; ni++)
                    MMA_TF32(acc[mi][ni], a[mi][0], a[mi][1], a[mi][2], a[mi][3],
                             b[ni][0], b[ni][1]);
        }
        __syncthreads();
    }

    #pragma unroll
    for (int mi = 0; mi < 2; mi++) {
        int rbase = row0 + m0 + mi * 16 + grp;
        #pragma unroll
        for (int ni = 0; ni < 4; ni++) {
            int col = n0 + ni * 8 + 2 * tig;
            if (rbase < M) {
                float2 v0 = make_float2(acc[mi][ni][0], acc[mi][ni][1]);
                *(float2*)&C[(size_t)rbase * BN + col] = v0;
            }
            if (rbase + 8 < M) {
                float2 v1 = make_float2(acc[mi][ni][2], acc[mi][ni][3]);
                *(float2*)&C[(size_t)(rbase + 8) * BN + col] = v1;
            }
        }
    }
}

// ---------------- 3xtf32 tensor GEMM3 (error-compensated, fp32-class) -------
// out = relu(a2*t+c2) @ W2 + b2; BN2 coefficients computed inline.
__global__ __launch_bounds__(256) void tgemm3_kernel(
    const float* __restrict__ A, const float* __restrict__ B, float* __restrict__ C,
    int M, const float* __restrict__ sum, const float* __restrict__ sq,
    const float* __restrict__ gamma, const float* __restrict__ beta,
    const float* __restrict__ bias) {
    constexpr int BM = 128, BN = 64, BK = 16, K = 64;
    __shared__ uint32_t Ah[BM][BK + 4], Al[BM][BK + 4];
    __shared__ uint32_t Bh[BK][BN + 8], Bl[BK][BN + 8];
    __shared__ float s_sc[K], s_sh[K], s_b[BN];

    int tid = threadIdx.x;
    if (tid < K) {
        float mean = sum[tid] / (float)M;
        float var  = sq[tid] / (float)M - mean * mean;
        float s = gamma[tid] * rsqrtf(var + BN_EPS);
        s_sc[tid] = s;
        s_sh[tid] = beta[tid] - mean * s;
    }
    if (tid < BN) s_b[tid] = bias[tid];

    int lane = tid & 31, wid = tid >> 5;
    int wr = wid & 3, wc = wid >> 2;
    int m0 = wr * 32, n0 = wc * 32;
    int row0 = blockIdx.x * BM;
    int grp = lane >> 2, tig = lane & 3;
    __syncthreads();

    float acc[2][4][4];
    #pragma unroll
    for (int i = 0; i < 2; i++)
        #pragma unroll
        for (int j = 0; j < 4; j++)
            #pragma unroll
            for (int r = 0; r < 4; r++) acc[i][j][r] = 0.f;

    for (int k0 = 0; k0 < K; k0 += BK) {
        #pragma unroll
        for (int p = 0; p < 2; p++) {
            int f = tid + p * 256;
            int r = f >> 2;
            int c4 = (f & 3) * 4;
            float4 v = make_float4(0.f, 0.f, 0.f, 0.f);
            if (row0 + r < M) v = *(const float4*)&A[(size_t)(row0 + r) * K + k0 + c4];
            int kb = k0 + c4;
            v.x = fmaxf(fmaf(v.x, s_sc[kb + 0], s_sh[kb + 0]), 0.f);
            v.y = fmaxf(fmaf(v.y, s_sc[kb + 1], s_sh[kb + 1]), 0.f);
            v.z = fmaxf(fmaf(v.z, s_sc[kb + 2], s_sh[kb + 2]), 0.f);
            v.w = fmaxf(fmaf(v.w, s_sc[kb + 3], s_sh[kb + 3]), 0.f);
            uint32_t hx = f_tf32(v.x), hy = f_tf32(v.y), hz = f_tf32(v.z), hw = f_tf32(v.w);
            Ah[r][c4 + 0] = hx; Ah[r][c4 + 1] = hy; Ah[r][c4 + 2] = hz; Ah[r][c4 + 3] = hw;
            Al[r][c4 + 0] = f_tf32(v.x - __uint_as_float(hx));
            Al[r][c4 + 1] = f_tf32(v.y - __uint_as_float(hy));
            Al[r][c4 + 2] = f_tf32(v.z - __uint_as_float(hz));
            Al[r][c4 + 3] = f_tf32(v.w - __uint_as_float(hw));
        }
        {
            int kr = tid >> 4;
            int c4 = (tid & 15) * 4;
            float4 v = *(const float4*)&B[(size_t)(k0 + kr) * BN + c4];
            uint32_t hx = f_tf32(v.x), hy = f_tf32(v.y), hz = f_tf32(v.z), hw = f_tf32(v.w);
            Bh[kr][c4 + 0] = hx; Bh[kr][c4 + 1] = hy; Bh[kr][c4 + 2] = hz; Bh[kr][c4 + 3] = hw;
            Bl[kr][c4 + 0] = f_tf32(v.x - __uint_as_float(hx));
            Bl[kr][c4 + 1] = f_tf32(v.y - __uint_as_float(hy));
            Bl[kr][c4 + 2] = f_tf32(v.z - __uint_as_float(hz));
            Bl[kr][c4 + 3] = f_tf32(v.w - __uint_as_float(hw));
        }
        __syncthreads();

        #pragma unroll
        for (int ks = 0; ks < BK / 8; ks++) {
            int kb = ks * 8;
            uint32_t ah[2][4], al[2][4];
            #pragma unroll
            for (int mi = 0; mi < 2; mi++) {
                int r = m0 + mi * 16 + grp;
                ah[mi][0] = Ah[r    ][kb + tig    ];
                ah[mi][1] = Ah[r + 8][kb + tig    ];
                ah[mi][2] = Ah[r    ][kb + tig + 4];
                ah[mi][3] = Ah[r + 8][kb + tig + 4];
                al[mi][0] = Al[r    ][kb + tig    ];
                al[mi][1] = Al[r + 8][kb + tig    ];
                al[mi][2] = Al[r    ][kb + tig + 4];
                al[mi][3] = Al[r + 8][kb + tig + 4];
            }
            uint32_t bh[4][2], bl[4][2];
            #pragma unroll
            for (int ni = 0; ni < 4; ni++) {
                int n = n0 + ni * 8 + grp;
                bh[ni][0] = Bh[kb + tig    ][n];
                bh[ni][1] = Bh[kb + tig + 4][n];
                bl[ni][0] = Bl[kb + tig    ][n];
                bl[ni][1] = Bl[kb + tig + 4][n];
            }
            #pragma unroll
            for (int mi = 0; mi < 2; mi++)
                #pragma unroll
                for (int ni = 0; ni < 4; ni++) {
                    MMA_TF32(acc[mi][ni], al[mi][0], al[mi][1], al[mi][2], al[mi][3],
                             bh[ni][0], bh[ni][1]);
                    MMA_TF32(acc[mi][ni], ah[mi][0], ah[mi][1], ah[mi][2], ah[mi][3],
                             bl[ni][0], bl[ni][1]);
                    MMA_TF32(acc[mi][ni], ah[mi][0], ah[mi][1], ah[mi][2], ah[mi][3],
                             bh[ni][0], bh[ni][1]);
                }
        }
        __syncthreads();
    }

    #pragma unroll
    for (int mi = 0; mi < 2; mi++) {
        int rbase = row0 + m0 + mi * 16 + grp;
        #pragma unroll
        for (int ni = 0; ni < 4; ni++) {
            int col = n0 + ni * 8 + 2 * tig;
            float b0 = s_b[col], b1 = s_b[col + 1];
            if (rbase < M) {
                float2 v0 = make_float2(acc[mi][ni][0] + b0, acc[mi][ni][1] + b1);
                *(float2*)&C[(size_t)rbase * BN + col] = v0;
            }
            if (rbase + 8 < M) {
                float2 v1 = make_float2(acc[mi][ni][2] + b0, acc[mi][ni][3] + b1);
                *(float2*)&C[(size_t)(rbase + 8) * BN + col] = v1;
            }
        }
    }
}

// ---------------- launch ----------------------------------------------------
extern "C" void kernel_launch(void* const* d_in, const int* in_sizes, int n_in,
                              void* d_out, int out_size) {
    const float* x     = (const float*)d_in[0];
    const int*   ei    = (const int*)d_in[1];
    const float* W_gcn = (const float*)d_in[2];
    // d_in[3] = b_gcn : exactly absorbed by BN1 (mean-subtraction) -> unused
    const float* bn_g  = (const float*)d_in[4];
    const float* bn_b  = (const float*)d_in[5];
    const float* W1    = (const float*)d_in[6];
    // d_in[7] = b1    : exactly absorbed by BN2 -> unused
    const float* mg    = (const float*)d_in[8];
    const float* mb    = (const float*)d_in[9];
    const float* W2    = (const float*)d_in[10];
    const float* b2    = (const float*)d_in[11];
    float* out = (float*)d_out;

    int M = in_sizes[0] / FIN;
    int E = in_sizes[1] / 2;
    const int* src = ei;
    const int* dst = ei + E;

    void *p_h, *p_agg, *p_t, *p_sum1, *p_sq1, *p_sum2, *p_sq2;
    cudaGetSymbolAddress(&p_h, g_h);
    cudaGetSymbolAddress(&p_agg, g_agg);
    cudaGetSymbolAddress(&p_t, g_t);
    cudaGetSymbolAddress(&p_sum1, g_sum1);
    cudaGetSymbolAddress(&p_sq1, g_sq1);
    cudaGetSymbolAddress(&p_sum2, g_sum2);
    cudaGetSymbolAddress(&p_sq2, g_sq2);

    // side stream + fork/join events; created once, reused every call.
    static cudaStream_t s_side = nullptr;
    static cudaEvent_t s_evFork = nullptr, s_evJoin = nullptr;
    if (s_side == nullptr) {
        cudaStreamCreateWithFlags(&s_side, cudaStreamNonBlocking);
        cudaEventCreateWithFlags(&s_evFork, cudaEventDisableTiming);
        cudaEventCreateWithFlags(&s_evJoin, cudaEventDisableTiming);
    }

    // main: zero (needed by both branches)
    zero_kernel<<<256, 256>>>(M);

    // fork: index machinery on side stream, overlapped with tgemm1 on main
    cudaEventRecord(s_evFork, 0);
    cudaStreamWaitEvent(s_side, s_evFork, 0);
    deg_kernel<<<(E + 255) / 256, 256, 0, s_side>>>(dst, E, M);
    alloc_kernel<<<(M + 255) / 256, 256, 0, s_side>>>(M);
    fill_kernel<<<(E + 255) / 256, 256, 0, s_side>>>(src, dst, E, M);
    cudaEventRecord(s_evJoin, s_side);

    // main: GEMM1 (tf32): h = x @ W_gcn
    tgemm1_kernel<<<(M + 127) / 128, 256>>>(x, W_gcn, (float*)p_h, M);

    // join: gather needs h + CSR + dinv
    cudaStreamWaitEvent(0, s_evJoin, 0);
    gather_kernel<<<(M * 32 + 255) / 256, 256>>>(M);

    // BN1 stats (finalize folded into tgemm2)
    stats_kernel<FIN><<<1024, 256>>>((const float*)p_agg, M, (float*)p_sum1, (float*)p_sq1);

    // GEMM2 (tf32, inline BN1): t = relu(BN1(agg)) @ W1
    tgemm2_kernel<<<(M + 127) / 128, 256>>>(
        (const float*)p_agg, W1, (float*)p_t, M,
        (const float*)p_sum1, (const float*)p_sq1, bn_g, bn_b);

    // BN2 stats (finalize folded into tgemm3)
    stats_kernel<FOUT><<<1024, 256>>>((const float*)p_t, M, (float*)p_sum2, (float*)p_sq2);

    // GEMM3 (3xtf32, inline BN2): out = relu(BN2(t)) @ W2 + b2
    tgemm3_kernel<<<(M + 127) / 128, 256>>>(
        (const float*)p_t, W2, out, M,
        (const float*)p_sum2, (const float*)p_sq2, mg, mb, b2);
}